// round 5
// baseline (speedup 1.0000x reference)
#include <cuda_runtime.h>
#include <cstdint>

// Problem constants
#define LL 2
#define BB 16
#define TT 512
#define HH 12
#define NL 4096   // (1+1)^12 leaves
#define NC 1000
#define NCHUNK 32 // token chunks per batch
#define TOKC 16   // tokens per chunk

// Scratch
__device__ float g_part[NCHUNK * BB * NL];  // [chunk][batch][leaf] (8 MB)
__device__ float g_avg[BB * NL];            // [batch][leaf] (256 KB)

// ---- f32x2 helpers ---------------------------------------------------------
__device__ __forceinline__ unsigned long long pk2(float x, float y) {
    unsigned long long r;
    asm("mov.b64 %0, {%1, %2};" : "=l"(r) : "f"(x), "f"(y));
    return r;
}
__device__ __forceinline__ void fma2(unsigned long long& d,
                                     unsigned long long a,
                                     unsigned long long b) {
    asm("fma.rn.f32x2 %0, %1, %2, %0;" : "+l"(d) : "l"(a), "l"(b));
}
__device__ __forceinline__ void upk2(unsigned long long v, float& lo, float& hi) {
    asm("mov.b64 {%0, %1}, %2;" : "=f"(lo), "=f"(hi) : "l"(v));
}

// ---- cp.async helpers ------------------------------------------------------
__device__ __forceinline__ uint32_t smem_u32(const void* p) {
    uint32_t a;
    asm("{ .reg .u64 t; cvta.to.shared.u64 t, %1; cvt.u32.u64 %0, t; }"
        : "=r"(a) : "l"(p));
    return a;
}
__device__ __forceinline__ void cp_async16(uint32_t dst, const void* src, int sz) {
    asm volatile("cp.async.cg.shared.global [%0], [%1], 16, %2;"
                 :: "r"(dst), "l"(src), "r"(sz));
}
__device__ __forceinline__ void cp_commit() {
    asm volatile("cp.async.commit_group;");
}
template <int N> __device__ __forceinline__ void cp_wait() {
    asm volatile("cp.async.wait_group %0;" :: "n"(N));
}

// ---------------------------------------------------------------------------
// Kernel 1: per-(batch, token-chunk) partial mean-leaf vectors, disjoint STG.
// grid = B * NCHUNK = 512 blocks, 256 threads. Also zeroes `out`.
// ---------------------------------------------------------------------------
__global__ __launch_bounds__(256) void leaf_kernel(
    const float* __restrict__ x, const float* __restrict__ cuts,
    float* __restrict__ out)
{
    const int tid = threadIdx.x;
    const int gid = blockIdx.x * 256 + tid;
    if (gid < BB * NC) out[gid] = 0.f;

    const int b     = blockIdx.x >> 5;         // batch
    const int chunk = blockIdx.x & 31;         // token chunk of 16

    __shared__ float P[TOKC * 128];            // [tok][half*64 + u]  (8 KB)
    __shared__ float sx[TOKC * 12];
    __shared__ float sc[12];

    if (tid < 12) sc[tid] = cuts[tid];

    const float* xl = x + (size_t)(LL - 1) * BB * TT * HH
                        + ((size_t)b * TT + (size_t)chunk * TOKC) * HH;
    for (int i = tid; i < TOKC * 12; i += 256) sx[i] = xl[i];
    __syncthreads();

    // Phase A: TOKC tokens x 2 halves x 64 half-leaf products
    for (int e = tid; e < TOKC * 128; e += 256) {
        const int tok  = e >> 7;
        const int half = (e >> 6) & 1;
        const int u    = e & 63;
        const float* xr = sx + tok * 12 + half * 6;
        const float* cr = sc + half * 6;
        float p = 1.f;
#pragma unroll
        for (int i = 0; i < 6; i++) {
            const float xv = xr[i];
            const float f  = ((u >> (5 - i)) & 1) ? fmaf(2.f, xv, -cr[i]) : xv;
            p *= f;
        }
        P[e] = p;
    }
    __syncthreads();

    // Phase B: rank-1 accumulation; hi products read directly as packed pairs
    const int w = tid >> 5, lane = tid & 31;
    unsigned long long acc2[4][2];
#pragma unroll
    for (int p = 0; p < 4; p++) { acc2[p][0] = 0ull; acc2[p][1] = 0ull; }

#pragma unroll 4
    for (int tok = 0; tok < TOKC; tok++) {
        const float* Pr = P + tok * 128;
        const ulonglong2* ph = (const ulonglong2*)(Pr + 8 * w);
        const ulonglong2 h0 = ph[0];   // (p0,p1) (p2,p3)
        const ulonglong2 h1 = ph[1];   // (p4,p5) (p6,p7)
        const float plo0 = Pr[64 + lane];
        const float plo1 = Pr[64 + lane + 32];
        const unsigned long long pl0 = pk2(plo0, plo0);
        const unsigned long long pl1 = pk2(plo1, plo1);
        fma2(acc2[0][0], h0.x, pl0); fma2(acc2[0][1], h0.x, pl1);
        fma2(acc2[1][0], h0.y, pl0); fma2(acc2[1][1], h0.y, pl1);
        fma2(acc2[2][0], h1.x, pl0); fma2(acc2[2][1], h1.x, pl1);
        fma2(acc2[3][0], h1.y, pl0); fma2(acc2[3][1], h1.y, pl1);
    }

    const float s = 1.f / (float)TT;
    float* dst = g_part + ((size_t)(chunk * BB + b)) * NL;
#pragma unroll
    for (int p = 0; p < 4; p++) {
        float u0v0, u1v0, u0v1, u1v1;
        upk2(acc2[p][0], u0v0, u1v0);
        upk2(acc2[p][1], u0v1, u1v1);
        const int u0 = 8 * w + 2 * p;
        dst[u0 * 64 + lane]            = u0v0 * s;
        dst[u0 * 64 + lane + 32]       = u0v1 * s;
        dst[(u0 + 1) * 64 + lane]      = u1v0 * s;
        dst[(u0 + 1) * 64 + lane + 32] = u1v1 * s;
    }
}

// ---------------------------------------------------------------------------
// Kernel 2: reduce 32 chunk partials -> g_avg[16][4096]. 8 MB read, float4.
// grid = 64 blocks x 256 threads; each thread owns 4 leaves.
// ---------------------------------------------------------------------------
__global__ __launch_bounds__(256) void reduce_kernel()
{
    const int i4 = blockIdx.x * 256 + threadIdx.x;   // 0 .. 16383 (float4 id)
    const float4* src = (const float4*)g_part + i4;
    float4 v = make_float4(0.f, 0.f, 0.f, 0.f);
#pragma unroll
    for (int ch = 0; ch < NCHUNK; ch++) {
        const float4 t = src[(size_t)ch * (BB * NL / 4)];
        v.x += t.x; v.y += t.y; v.z += t.z; v.w += t.w;
    }
    ((float4*)g_avg)[i4] = v;
}

// ---------------------------------------------------------------------------
// Kernel 3: out[16,1000] += g_avg[16,4096] @ score[4096,1000].
// grid = (64, 8), 128 threads. Score via 4-stage cp.async pipeline.
// ---------------------------------------------------------------------------
#define G_LCH  64
#define G_CT   128
#define SROWS  16
#define NSTAGE 4

__global__ __launch_bounds__(128) void gemm_out_kernel(
    const float* __restrict__ score, float* __restrict__ out)
{
    __shared__ float sS[G_LCH * G_CT];   // 32 KB
    __shared__ float sA[G_LCH * 16];     // 4 KB [l][b]

    const int tid = threadIdx.x;
    const int l0  = blockIdx.x * G_LCH;
    const int c0  = blockIdx.y * G_CT;
    const uint32_t sS_base = smem_u32(sS);

#pragma unroll
    for (int s = 0; s < NSTAGE; s++) {
#pragma unroll
        for (int t = 0; t < 4; t++) {
            const int k  = tid + t * 128;
            const int r  = k >> 5;
            const int cc = k & 31;
            const int col = c0 + cc * 4;
            const char* src = (const char*)score
                + (size_t)(l0 + s * SROWS + r) * (NC * 4) + (size_t)col * 4;
            const uint32_t dst = sS_base
                + (uint32_t)(((s * SROWS + r) * G_CT + cc * 4) * 4);
            const int sz = (col + 4 <= NC) ? 16 : 0;
            cp_async16(dst, src, sz);
        }
        cp_commit();
    }

    for (int e = tid; e < 16 * G_LCH; e += 128) {
        const int bb = e >> 6;
        const int l  = e & (G_LCH - 1);
        sA[l * 16 + bb] = g_avg[bb * NL + l0 + l];
    }

    unsigned long long acc[8];
#pragma unroll
    for (int p = 0; p < 8; p++) acc[p] = 0ull;

    const int c = c0 + tid;

#pragma unroll
    for (int s = 0; s < NSTAGE; s++) {
        if (s == 0) cp_wait<3>();
        else if (s == 1) cp_wait<2>();
        else if (s == 2) cp_wait<1>();
        else cp_wait<0>();
        __syncthreads();

#pragma unroll
        for (int r = 0; r < SROWS; r++) {
            const int l = s * SROWS + r;
            const float sv = sS[l * G_CT + tid];
            const unsigned long long ss = pk2(sv, sv);
            const ulonglong2* ar = (const ulonglong2*)(sA + l * 16);
            const ulonglong2 q0 = ar[0];
            const ulonglong2 q1 = ar[1];
            const ulonglong2 q2 = ar[2];
            const ulonglong2 q3 = ar[3];
            fma2(acc[0], ss, q0.x); fma2(acc[1], ss, q0.y);
            fma2(acc[2], ss, q1.x); fma2(acc[3], ss, q1.y);
            fma2(acc[4], ss, q2.x); fma2(acc[5], ss, q2.y);
            fma2(acc[6], ss, q3.x); fma2(acc[7], ss, q3.y);
        }
    }

    if (c < NC) {
#pragma unroll
        for (int p = 0; p < 8; p++) {
            float blo, bhi;
            upk2(acc[p], blo, bhi);
            atomicAdd(out + (2 * p) * NC + c,     blo);
            atomicAdd(out + (2 * p + 1) * NC + c, bhi);
        }
    }
}

// ---------------------------------------------------------------------------
extern "C" void kernel_launch(void* const* d_in, const int* in_sizes, int n_in,
                              void* d_out, int out_size)
{
    const float* x     = (const float*)d_in[0];  // (2,16,512,12)
    const float* cuts  = (const float*)d_in[1];  // (12,1)
    const float* score = (const float*)d_in[2];  // (4096,1000)
    float* out = (float*)d_out;                  // (16,1000)

    leaf_kernel<<<BB * NCHUNK, 256>>>(x, cuts, out);
    reduce_kernel<<<BB * NL / (256 * 4), 256>>>();
    dim3 g3(NL / G_LCH, (NC + G_CT - 1) / G_CT);   // (64, 8)
    gemm_out_kernel<<<g3, 128>>>(score, out);
}

// round 6
// speedup vs baseline: 1.2280x; 1.2280x over previous
#include <cuda_runtime.h>
#include <cstdint>

// Problem constants
#define LL 2
#define BB 16
#define TT 512
#define HH 12
#define NL 4096   // (1+1)^12 leaves
#define NC 1000
#define NCHUNK 16 // token chunks per batch
#define TOKC 32   // tokens per chunk

// Scratch: [chunk][batch][leaf]  (4 MB)
__device__ float g_part[NCHUNK * BB * NL];

// ---- f32x2 helpers ---------------------------------------------------------
__device__ __forceinline__ unsigned long long pk2(float x, float y) {
    unsigned long long r;
    asm("mov.b64 %0, {%1, %2};" : "=l"(r) : "f"(x), "f"(y));
    return r;
}
__device__ __forceinline__ void fma2(unsigned long long& d,
                                     unsigned long long a,
                                     unsigned long long b) {
    asm("fma.rn.f32x2 %0, %1, %2, %0;" : "+l"(d) : "l"(a), "l"(b));
}
__device__ __forceinline__ void upk2(unsigned long long v, float& lo, float& hi) {
    asm("mov.b64 {%0, %1}, %2;" : "=f"(lo), "=f"(hi) : "l"(v));
}

// ---- cp.async helpers ------------------------------------------------------
__device__ __forceinline__ uint32_t smem_u32(const void* p) {
    uint32_t a;
    asm("{ .reg .u64 t; cvta.to.shared.u64 t, %1; cvt.u32.u64 %0, t; }"
        : "=r"(a) : "l"(p));
    return a;
}
__device__ __forceinline__ void cp_async16(uint32_t dst, const void* src, int sz) {
    asm volatile("cp.async.cg.shared.global [%0], [%1], 16, %2;"
                 :: "r"(dst), "l"(src), "r"(sz));
}
__device__ __forceinline__ void cp_commit() {
    asm volatile("cp.async.commit_group;");
}
template <int N> __device__ __forceinline__ void cp_wait() {
    asm volatile("cp.async.wait_group %0;" :: "n"(N));
}

// ---------------------------------------------------------------------------
// Kernel 1: per-(batch, token-chunk) partial mean-leaf vectors, disjoint STG.
// grid = B * NCHUNK = 256 blocks, 256 threads. Also zeroes `out`.
// Leaf l = u*64+v; u bits = levels 0-5 (bit 5-i), v bits = levels 6-11.
// f(i,0)=x_i, f(i,1)=2*x_i - c_i.
// ---------------------------------------------------------------------------
__global__ __launch_bounds__(256) void leaf_kernel(
    const float* __restrict__ x, const float* __restrict__ cuts,
    float* __restrict__ out)
{
    const int tid = threadIdx.x;
    const int gid = blockIdx.x * 256 + tid;    // 256*256 = 65536 >= 16000
    if (gid < BB * NC) out[gid] = 0.f;

    const int b     = blockIdx.x >> 4;         // batch
    const int chunk = blockIdx.x & 15;         // token chunk of 32

    __shared__ float P[TOKC * 128];            // [tok][half*64 + u]  (16 KB)
    __shared__ float sx[TOKC * 12];
    __shared__ float sc[12];

    if (tid < 12) sc[tid] = cuts[tid];

    const float* xl = x + (size_t)(LL - 1) * BB * TT * HH
                        + ((size_t)b * TT + (size_t)chunk * TOKC) * HH;
    for (int i = tid; i < TOKC * 12; i += 256) sx[i] = xl[i];
    __syncthreads();

    // Phase A: 512 tasks (tok, half, g); each emits 8 contiguous products.
    // Thread owns fixed (half, g) and two tokens (tid>>4, +16).
    {
        const int half = (tid >> 3) & 1;
        const int g    = tid & 7;                 // u high 3 bits
        const float* cr = sc + half * 6;
        const float c0 = cr[0], c1 = cr[1], c2 = cr[2];
        const float c3 = cr[3], c4 = cr[4], c5 = cr[5];
#pragma unroll
        for (int t2 = 0; t2 < 2; t2++) {
            const int tok = (tid >> 4) + t2 * 16;
            const float* xr = sx + tok * 12 + half * 6;
            const float x0 = xr[0], x1 = xr[1], x2 = xr[2];
            const float x3 = xr[3], x4 = xr[4], x5 = xr[5];
            // prefix over levels 0..2 selected by g bits 2,1,0
            const float F0 = (g & 4) ? fmaf(2.f, x0, -c0) : x0;
            const float F1 = (g & 2) ? fmaf(2.f, x1, -c1) : x1;
            const float F2 = (g & 1) ? fmaf(2.f, x2, -c2) : x2;
            const float p  = F0 * F1 * F2;
            // doubling tree over levels 3..5
            const float b3 = fmaf(2.f, x3, -c3);
            const float a4 = x4, b4 = fmaf(2.f, x4, -c4);
            const float a5 = x5, b5 = fmaf(2.f, x5, -c5);
            const float m00 = a4 * a5, m01 = a4 * b5;
            const float m10 = b4 * a5, m11 = b4 * b5;
            const float q0 = p * x3, q1 = p * b3;
            float* dst = P + tok * 128 + half * 64 + g * 8;
            *(float4*)dst       = make_float4(q0 * m00, q0 * m01, q0 * m10, q0 * m11);
            *(float4*)(dst + 4) = make_float4(q1 * m00, q1 * m01, q1 * m10, q1 * m11);
        }
    }
    __syncthreads();

    // Phase B: rank-1 accumulation; hi products read directly as packed pairs
    const int w = tid >> 5, lane = tid & 31;
    unsigned long long acc2[4][2];
#pragma unroll
    for (int p = 0; p < 4; p++) { acc2[p][0] = 0ull; acc2[p][1] = 0ull; }

#pragma unroll 4
    for (int tok = 0; tok < TOKC; tok++) {
        const float* Pr = P + tok * 128;
        const ulonglong2* ph = (const ulonglong2*)(Pr + 8 * w);
        const ulonglong2 h0 = ph[0];
        const ulonglong2 h1 = ph[1];
        const float plo0 = Pr[64 + lane];
        const float plo1 = Pr[64 + lane + 32];
        const unsigned long long pl0 = pk2(plo0, plo0);
        const unsigned long long pl1 = pk2(plo1, plo1);
        fma2(acc2[0][0], h0.x, pl0); fma2(acc2[0][1], h0.x, pl1);
        fma2(acc2[1][0], h0.y, pl0); fma2(acc2[1][1], h0.y, pl1);
        fma2(acc2[2][0], h1.x, pl0); fma2(acc2[2][1], h1.x, pl1);
        fma2(acc2[3][0], h1.y, pl0); fma2(acc2[3][1], h1.y, pl1);
    }

    const float s = 1.f / (float)TT;
    float* dst = g_part + ((size_t)(chunk * BB + b)) * NL;
#pragma unroll
    for (int p = 0; p < 4; p++) {
        float u0v0, u1v0, u0v1, u1v1;
        upk2(acc2[p][0], u0v0, u1v0);
        upk2(acc2[p][1], u0v1, u1v1);
        const int u0 = 8 * w + 2 * p;
        dst[u0 * 64 + lane]            = u0v0 * s;
        dst[u0 * 64 + lane + 32]       = u0v1 * s;
        dst[(u0 + 1) * 64 + lane]      = u1v0 * s;
        dst[(u0 + 1) * 64 + lane + 32] = u1v1 * s;
    }
}

// ---------------------------------------------------------------------------
// Kernel 2: out[16,1000] += avg[16,4096] @ score[4096,1000].
// grid = (64, 8), 128 threads. Score via 4-stage cp.async pipeline.
// sA built inline by reducing the 16 L2-hot chunk partials (float4 loads).
// ---------------------------------------------------------------------------
#define G_LCH  64
#define G_CT   128
#define SROWS  16
#define NSTAGE 4

__global__ __launch_bounds__(128) void gemm_out_kernel(
    const float* __restrict__ score, float* __restrict__ out)
{
    __shared__ float sS[G_LCH * G_CT];   // 32 KB
    __shared__ float sA[G_LCH * 16];     // 4 KB [l][b]

    const int tid = threadIdx.x;
    const int l0  = blockIdx.x * G_LCH;
    const int c0  = blockIdx.y * G_CT;
    const uint32_t sS_base = smem_u32(sS);

    // Issue all 4 stages of async score loads up front (32 KB in flight).
#pragma unroll
    for (int s = 0; s < NSTAGE; s++) {
#pragma unroll
        for (int t = 0; t < 4; t++) {
            const int k  = tid + t * 128;
            const int r  = k >> 5;
            const int cc = k & 31;
            const int col = c0 + cc * 4;
            const char* src = (const char*)score
                + (size_t)(l0 + s * SROWS + r) * (NC * 4) + (size_t)col * 4;
            const uint32_t dst = sS_base
                + (uint32_t)(((s * SROWS + r) * G_CT + cc * 4) * 4);
            const int sz = (col + 4 <= NC) ? 16 : 0;
            cp_async16(dst, src, sz);
        }
        cp_commit();
    }

    // Inline reduce: sA[l][b] = sum_ch g_part[ch][b][l0+l] (L2-hot, float4)
    for (int e = tid; e < 256; e += 128) {
        const int bb = e >> 4;           // batch 0..15
        const int lq = e & 15;           // leaf quad 0..15
        const float4* p = (const float4*)(g_part + (size_t)bb * NL + l0) + lq;
        float4 v = make_float4(0.f, 0.f, 0.f, 0.f);
#pragma unroll
        for (int ch = 0; ch < NCHUNK; ch++) {
            const float4 t = p[(size_t)ch * (BB * NL / 4)];
            v.x += t.x; v.y += t.y; v.z += t.z; v.w += t.w;
        }
        sA[(lq * 4 + 0) * 16 + bb] = v.x;
        sA[(lq * 4 + 1) * 16 + bb] = v.y;
        sA[(lq * 4 + 2) * 16 + bb] = v.z;
        sA[(lq * 4 + 3) * 16 + bb] = v.w;
    }

    unsigned long long acc[8];
#pragma unroll
    for (int p = 0; p < 8; p++) acc[p] = 0ull;

    const int c = c0 + tid;

#pragma unroll
    for (int s = 0; s < NSTAGE; s++) {
        if (s == 0) cp_wait<3>();
        else if (s == 1) cp_wait<2>();
        else if (s == 2) cp_wait<1>();
        else cp_wait<0>();
        __syncthreads();

#pragma unroll
        for (int r = 0; r < SROWS; r++) {
            const int l = s * SROWS + r;
            const float sv = sS[l * G_CT + tid];
            const unsigned long long ss = pk2(sv, sv);
            const ulonglong2* ar = (const ulonglong2*)(sA + l * 16);
            const ulonglong2 q0 = ar[0];
            const ulonglong2 q1 = ar[1];
            const ulonglong2 q2 = ar[2];
            const ulonglong2 q3 = ar[3];
            fma2(acc[0], ss, q0.x); fma2(acc[1], ss, q0.y);
            fma2(acc[2], ss, q1.x); fma2(acc[3], ss, q1.y);
            fma2(acc[4], ss, q2.x); fma2(acc[5], ss, q2.y);
            fma2(acc[6], ss, q3.x); fma2(acc[7], ss, q3.y);
        }
    }

    if (c < NC) {
#pragma unroll
        for (int p = 0; p < 8; p++) {
            float blo, bhi;
            upk2(acc[p], blo, bhi);
            atomicAdd(out + (2 * p) * NC + c,     blo);
            atomicAdd(out + (2 * p + 1) * NC + c, bhi);
        }
    }
}

// ---------------------------------------------------------------------------
extern "C" void kernel_launch(void* const* d_in, const int* in_sizes, int n_in,
                              void* d_out, int out_size)
{
    const float* x     = (const float*)d_in[0];  // (2,16,512,12)
    const float* cuts  = (const float*)d_in[1];  // (12,1)
    const float* score = (const float*)d_in[2];  // (4096,1000)
    float* out = (float*)d_out;                  // (16,1000)

    leaf_kernel<<<BB * NCHUNK, 256>>>(x, cuts, out);
    dim3 g3(NL / G_LCH, (NC + G_CT - 1) / G_CT);   // (64, 8)
    gemm_out_kernel<<<g3, 128>>>(score, out);
}